// round 14
// baseline (speedup 1.0000x reference)
#include <cuda_runtime.h>
#include <cstdint>

// out[n,d] = mean_f( x[n,f]*W[f,d] + b[f,d] ) = (x@W + 1^T b)[n,d] / 256
// N=8192, K=256, D=64. Single kernel. bf16 3-term split on mma.sync m16n8k16.
// Each warp: 16-row x 16-col tile, builds A- and B-fragments inline in
// registers (no smem, no barriers, no prep kernel). Bias folded into the GEMM
// via 16 extra MMA iterations with A = ones(bf16).

typedef uint32_t u32;

#define NF 256
#define ND 64
#define TILE_M 16
#define THREADS 128
#define NBLOCKS 512

__device__ __forceinline__ void cvt_split(float a, float b, u32& hi, u32& lo) {
    asm("cvt.rn.bf16x2.f32 %0, %1, %2;" : "=r"(hi) : "f"(b), "f"(a));
    float ha = __uint_as_float(hi << 16);
    float hb = __uint_as_float(hi & 0xFFFF0000u);
    float ra = a - ha;
    float rb = b - hb;
    asm("cvt.rn.bf16x2.f32 %0, %1, %2;" : "=r"(lo) : "f"(rb), "f"(ra));
}
__device__ __forceinline__ void mma16816(float* c, u32 a0, u32 a1, u32 a2, u32 a3,
                                         u32 b0, u32 b1) {
    asm volatile(
        "mma.sync.aligned.m16n8k16.row.col.f32.bf16.bf16.f32 "
        "{%0,%1,%2,%3}, {%4,%5,%6,%7}, {%8,%9}, {%0,%1,%2,%3};"
        : "+f"(c[0]), "+f"(c[1]), "+f"(c[2]), "+f"(c[3])
        : "r"(a0), "r"(a1), "r"(a2), "r"(a3), "r"(b0), "r"(b1));
}

__global__ void __launch_bounds__(THREADS, 4)
nanembed_kernel(const float* __restrict__ x, const float* __restrict__ W,
                const float* __restrict__ b, float* __restrict__ out)
{
    const int tid  = threadIdx.x;
    const int wid  = tid >> 5;
    const int lane = tid & 31;
    const int n0   = wid * 16;
    const int g    = lane >> 2;
    const int t4   = lane & 3;
    const int R    = blockIdx.x * TILE_M;

    const float* xr0 = x + (size_t)(R + g) * NF + 2 * t4;
    const float* xr8 = x + (size_t)(R + 8 + g) * NF + 2 * t4;
    const int colA = n0 + g;
    const int colB = n0 + 8 + g;
    const float* Wl = W + (2 * t4) * ND;   // + ki*16*ND per step
    const float* bl = b + (2 * t4) * ND;

    float a0hh[4]={0,0,0,0}, a0hl[4]={0,0,0,0}, a0lh[4]={0,0,0,0};
    float a1hh[4]={0,0,0,0}, a1hl[4]={0,0,0,0}, a1lh[4]={0,0,0,0};

    // ---- pipelines: x depth 4, W depth 2 ----
    float2 px[4][4];
    float  pw[2][8];
    #pragma unroll
    for (int p = 0; p < 4; ++p) {
        px[p][0] = *(const float2*)(xr0 + p * 16);
        px[p][1] = *(const float2*)(xr8 + p * 16);
        px[p][2] = *(const float2*)(xr0 + p * 16 + 8);
        px[p][3] = *(const float2*)(xr8 + p * 16 + 8);
    }
    #pragma unroll
    for (int p = 0; p < 2; ++p) {
        const float* wk = Wl + p * 16 * ND;
        pw[p][0] = wk[colA];          pw[p][1] = wk[ND + colA];
        pw[p][2] = wk[8 * ND + colA]; pw[p][3] = wk[9 * ND + colA];
        pw[p][4] = wk[colB];          pw[p][5] = wk[ND + colB];
        pw[p][6] = wk[8 * ND + colB]; pw[p][7] = wk[9 * ND + colB];
    }

    // ---- main GEMM: 16 k-iters ----
    #pragma unroll
    for (int ki = 0; ki < 16; ++ki) {
        const int sx = ki & 3, sw = ki & 1;
        float2 q0 = px[sx][0], q1 = px[sx][1], q2 = px[sx][2], q3 = px[sx][3];
        float w0a = pw[sw][0], w1a = pw[sw][1], w2a = pw[sw][2], w3a = pw[sw][3];
        float w0b = pw[sw][4], w1b = pw[sw][5], w2b = pw[sw][6], w3b = pw[sw][7];

        if (ki < 12) {
            px[sx][0] = *(const float2*)(xr0 + (ki + 4) * 16);
            px[sx][1] = *(const float2*)(xr8 + (ki + 4) * 16);
            px[sx][2] = *(const float2*)(xr0 + (ki + 4) * 16 + 8);
            px[sx][3] = *(const float2*)(xr8 + (ki + 4) * 16 + 8);
        }
        if (ki < 14) {
            const float* wk = Wl + (ki + 2) * 16 * ND;
            pw[sw][0] = wk[colA];          pw[sw][1] = wk[ND + colA];
            pw[sw][2] = wk[8 * ND + colA]; pw[sw][3] = wk[9 * ND + colA];
            pw[sw][4] = wk[colB];          pw[sw][5] = wk[ND + colB];
            pw[sw][6] = wk[8 * ND + colB]; pw[sw][7] = wk[9 * ND + colB];
        }

        u32 ah0, al0, ah1, al1, ah2, al2, ah3, al3;
        cvt_split(q0.x, q0.y, ah0, al0);
        cvt_split(q1.x, q1.y, ah1, al1);
        cvt_split(q2.x, q2.y, ah2, al2);
        cvt_split(q3.x, q3.y, ah3, al3);
        u32 h01a, l01a, h23a, l23a, h01b, l01b, h23b, l23b;
        cvt_split(w0a, w1a, h01a, l01a);
        cvt_split(w2a, w3a, h23a, l23a);
        cvt_split(w0b, w1b, h01b, l01b);
        cvt_split(w2b, w3b, h23b, l23b);

        mma16816(a0hh, ah0, ah1, ah2, ah3, h01a, h23a);
        mma16816(a1hh, ah0, ah1, ah2, ah3, h01b, h23b);
        mma16816(a0hl, ah0, ah1, ah2, ah3, l01a, l23a);
        mma16816(a1hl, ah0, ah1, ah2, ah3, l01b, l23b);
        mma16816(a0lh, al0, al1, al2, al3, h01a, h23a);
        mma16816(a1lh, al0, al1, al2, al3, h01b, h23b);
    }

    // ---- bias phase: A = ones(bf16), B = b hi/lo fragments, 16 iters ----
    const u32 ONE2 = 0x3F803F80u;   // bf16x2 {1.0, 1.0}
    float pb[2][8];
    #pragma unroll
    for (int p = 0; p < 2; ++p) {
        const float* bk = bl + p * 16 * ND;
        pb[p][0] = bk[colA];          pb[p][1] = bk[ND + colA];
        pb[p][2] = bk[8 * ND + colA]; pb[p][3] = bk[9 * ND + colA];
        pb[p][4] = bk[colB];          pb[p][5] = bk[ND + colB];
        pb[p][6] = bk[8 * ND + colB]; pb[p][7] = bk[9 * ND + colB];
    }
    #pragma unroll
    for (int ki = 0; ki < 16; ++ki) {
        const int c = ki & 1;
        float b0a = pb[c][0], b1a = pb[c][1], b2a = pb[c][2], b3a = pb[c][3];
        float b0b = pb[c][4], b1b = pb[c][5], b2b = pb[c][6], b3b = pb[c][7];
        if (ki < 14) {
            const float* bk = bl + (ki + 2) * 16 * ND;
            pb[c][0] = bk[colA];          pb[c][1] = bk[ND + colA];
            pb[c][2] = bk[8 * ND + colA]; pb[c][3] = bk[9 * ND + colA];
            pb[c][4] = bk[colB];          pb[c][5] = bk[ND + colB];
            pb[c][6] = bk[8 * ND + colB]; pb[c][7] = bk[9 * ND + colB];
        }
        u32 h01a, l01a, h23a, l23a, h01b, l01b, h23b, l23b;
        cvt_split(b0a, b1a, h01a, l01a);
        cvt_split(b2a, b3a, h23a, l23a);
        cvt_split(b0b, b1b, h01b, l01b);
        cvt_split(b2b, b3b, h23b, l23b);

        mma16816(a0hh, ONE2, ONE2, ONE2, ONE2, h01a, h23a);
        mma16816(a1hh, ONE2, ONE2, ONE2, ONE2, h01b, h23b);
        mma16816(a0hl, ONE2, ONE2, ONE2, ONE2, l01a, l23a);
        mma16816(a1hl, ONE2, ONE2, ONE2, ONE2, l01b, l23b);
    }

    // ---- epilogue: out = acc / 256 (bias already inside the accumulators) ----
    const float inv = 1.f / 256.f;
    const int grow = R + g;
    {
        int col = n0 + 2 * t4;
        float2 o0, o1;
        o0.x = (a0hh[0] + a0hl[0] + a0lh[0]) * inv;
        o0.y = (a0hh[1] + a0hl[1] + a0lh[1]) * inv;
        o1.x = (a0hh[2] + a0hl[2] + a0lh[2]) * inv;
        o1.y = (a0hh[3] + a0hl[3] + a0lh[3]) * inv;
        *(float2*)(out + (size_t)grow * ND + col) = o0;
        *(float2*)(out + (size_t)(grow + 8) * ND + col) = o1;
    }
    {
        int col = n0 + 8 + 2 * t4;
        float2 o0, o1;
        o0.x = (a1hh[0] + a1hl[0] + a1lh[0]) * inv;
        o0.y = (a1hh[1] + a1hl[1] + a1lh[1]) * inv;
        o1.x = (a1hh[2] + a1hl[2] + a1lh[2]) * inv;
        o1.y = (a1hh[3] + a1hl[3] + a1lh[3]) * inv;
        *(float2*)(out + (size_t)grow * ND + col) = o0;
        *(float2*)(out + (size_t)(grow + 8) * ND + col) = o1;
    }
}

extern "C" void kernel_launch(void* const* d_in, const int* in_sizes, int n_in,
                              void* d_out, int out_size)
{
    const float* x = (const float*)d_in[0];
    const float* W = (const float*)d_in[1];
    const float* b = (const float*)d_in[2];
    float* out = (float*)d_out;

    nanembed_kernel<<<NBLOCKS, THREADS>>>(x, W, b, out);
}

// round 15
// speedup vs baseline: 1.2786x; 1.2786x over previous
#include <cuda_runtime.h>
#include <cstdint>

// out[n,d] = mean_f( x[n,f]*W[f,d] + b[f,d] ) = (x@W)[n,d]/256 + mean_f b[f,d]
// N=8192, K=256, D=64. bf16 3-term split on tensor cores (mma.sync m16n8k16).
//
// transform: x -> AfH/AfL (A-fragments, bf16 hi/lo), W -> Wf (B-fragments),
//   b -> mb. main (PDL): smem-free, barrier-free; 512 CTAs x 8 warps,
//   N-split: warp w owns cols [w*8, w*8+8) of its 16-row tile (no reduction).

typedef uint32_t u32;

#define NROWS  8192
#define NF     256
#define ND     64
#define TILE_M 16
#define NTILES (NROWS / TILE_M)        // 512
#define TTHREADS 256
#define TBLOCKS (NTILES + 16 + 1)      // 529
#define MTHREADS 256
#define MBLOCKS NTILES                 // 512

// A-frag tables: [tile][ki][lane] uint4
__device__ uint4 AfH_g[NTILES * 16 * 32];
__device__ uint4 AfL_g[NTILES * 16 * 32];
// Wf[ki][col][t] : uint4 {hi(k=2t,2t+1), hi(k=2t+8,2t+9), lo(..), lo(..)}
__device__ uint4 Wf_g[16 * 64 * 4];
__device__ float mb_g[64];

__device__ __forceinline__ void cvt_split(float a, float b, u32& hi, u32& lo) {
    asm("cvt.rn.bf16x2.f32 %0, %1, %2;" : "=r"(hi) : "f"(b), "f"(a));
    float ha = __uint_as_float(hi << 16);
    float hb = __uint_as_float(hi & 0xFFFF0000u);
    float ra = a - ha;
    float rb = b - hb;
    asm("cvt.rn.bf16x2.f32 %0, %1, %2;" : "=r"(lo) : "f"(rb), "f"(ra));
}
__device__ __forceinline__ void mma16816(float* c, const uint4 a, u32 b0, u32 b1) {
    asm volatile(
        "mma.sync.aligned.m16n8k16.row.col.f32.bf16.bf16.f32 "
        "{%0,%1,%2,%3}, {%4,%5,%6,%7}, {%8,%9}, {%0,%1,%2,%3};"
        : "+f"(c[0]), "+f"(c[1]), "+f"(c[2]), "+f"(c[3])
        : "r"(a.x), "r"(a.y), "r"(a.z), "r"(a.w), "r"(b0), "r"(b1));
}

// ---------------- transform kernel ----------------
__global__ void __launch_bounds__(TTHREADS)
transform_kernel(const float* __restrict__ x,
                 const float* __restrict__ W,
                 const float* __restrict__ b)
{
    const int tid = threadIdx.x;
    const int bid = blockIdx.x;

    if (bid < NTILES) {
        // build A-fragments for tile bid: 512 entries, 2 per thread
        const int R = bid * TILE_M;
        #pragma unroll
        for (int e = 0; e < 2; ++e) {
            int idx  = e * TTHREADS + tid;     // 0..511
            int ki   = idx >> 5;
            int lane = idx & 31;
            int g    = lane >> 2;
            int t4   = lane & 3;
            int K    = ki * 16 + 2 * t4;
            const float* xr0 = x + (size_t)(R + g) * NF;
            const float* xr8 = x + (size_t)(R + 8 + g) * NF;
            float2 p0 = *(const float2*)(xr0 + K);
            float2 p1 = *(const float2*)(xr8 + K);
            float2 p2 = *(const float2*)(xr0 + K + 8);
            float2 p3 = *(const float2*)(xr8 + K + 8);
            u32 h0,l0,h1,l1,h2,l2,h3,l3;
            cvt_split(p0.x, p0.y, h0, l0);
            cvt_split(p1.x, p1.y, h1, l1);
            cvt_split(p2.x, p2.y, h2, l2);
            cvt_split(p3.x, p3.y, h3, l3);
            int o = (bid * 16 + ki) * 32 + lane;
            AfH_g[o] = make_uint4(h0, h1, h2, h3);
            AfL_g[o] = make_uint4(l0, l1, l2, l3);
        }
    } else if (bid < NTILES + 16) {
        int idx = (bid - NTILES) * 256 + tid;      // 0..4095
        int ki  = idx >> 8;
        int col = (idx >> 2) & 63;
        int t   = idx & 3;
        int k0  = ki * 16 + 2 * t;
        float w0 = W[(k0    ) * ND + col];
        float w1 = W[(k0 + 1) * ND + col];
        float w2 = W[(k0 + 8) * ND + col];
        float w3 = W[(k0 + 9) * ND + col];
        u32 h01, l01, h23, l23;
        cvt_split(w0, w1, h01, l01);
        cvt_split(w2, w3, h23, l23);
        Wf_g[idx] = make_uint4(h01, h23, l01, l23);
    } else {
        __shared__ float4 sc[256];
        const int qd = tid & 15;
        const int fr = tid >> 4;
        const float4* b4 = (const float4*)b;   // [256][16] float4
        float4 s = make_float4(0.f, 0.f, 0.f, 0.f);
        #pragma unroll
        for (int k = 0; k < 16; ++k) {
            float4 v = b4[(fr * 16 + k) * 16 + qd];
            s.x += v.x; s.y += v.y; s.z += v.z; s.w += v.w;
        }
        sc[tid] = s;
        __syncthreads();
        if (tid < 16) {
            float4 m = make_float4(0.f, 0.f, 0.f, 0.f);
            #pragma unroll
            for (int g = 0; g < 16; ++g) {
                float4 v = sc[tid + 16 * g];
                m.x += v.x; m.y += v.y; m.z += v.z; m.w += v.w;
            }
            const float inv = 1.f / 256.f;
            m.x *= inv; m.y *= inv; m.z *= inv; m.w *= inv;
            ((float4*)mb_g)[tid] = m;
        }
    }
    __threadfence();
    __syncthreads();
    asm volatile("griddepcontrol.launch_dependents;");
}

// ---------------- main kernel: 8 warps/tile (N-split), no smem/barriers ----
__global__ void __launch_bounds__(MTHREADS, 3)
nanembed_hmma_kernel(float* __restrict__ out)
{
    asm volatile("griddepcontrol.wait;");

    const int tid  = threadIdx.x;
    const int bid  = blockIdx.x;           // tile id
    const int wid  = tid >> 5;             // 0..7 -> col group
    const int lane = tid & 31;
    const int n0   = wid * 8;
    const int g    = lane >> 2;
    const int t4   = lane & 3;

    const uint4* aH = AfH_g + (bid * 16) * 32 + lane;   // stride 32/ki
    const uint4* aL = AfL_g + (bid * 16) * 32 + lane;
    const uint4* bp = Wf_g + ((n0 + g) * 4 + t4);       // stride 256/ki

    float ahh[4] = {0,0,0,0}, ahl[4] = {0,0,0,0}, alh[4] = {0,0,0,0};

    // 4-deep prefetch pipeline
    uint4 AH[4], AL[4], B0[4];
    #pragma unroll
    for (int p = 0; p < 4; ++p) {
        AH[p] = aH[p * 32];
        AL[p] = aL[p * 32];
        B0[p] = bp[p * 256];
    }

    #pragma unroll
    for (int ki = 0; ki < 16; ++ki) {
        const int s = ki & 3;
        uint4 ah = AH[s], al = AL[s], b0 = B0[s];
        if (ki < 12) {
            AH[s] = aH[(ki + 4) * 32];
            AL[s] = aL[(ki + 4) * 32];
            B0[s] = bp[(ki + 4) * 256];
        }
        mma16816(ahh, ah, b0.x, b0.y);   // hi*hi
        mma16816(ahl, ah, b0.z, b0.w);   // hi*lo
        mma16816(alh, al, b0.x, b0.y);   // lo*hi
    }

    // ---- epilogue ----
    const float inv = 1.f / 256.f;
    const int grow = bid * TILE_M + g;
    int col = n0 + 2 * t4;
    float2 m = *(const float2*)(mb_g + col);
    float s0 = ahh[0] + ahl[0] + alh[0];
    float s1 = ahh[1] + ahl[1] + alh[1];
    float s2 = ahh[2] + ahl[2] + alh[2];
    float s3 = ahh[3] + ahl[3] + alh[3];
    float2 o0, o1;
    o0.x = fmaf(s0, inv, m.x); o0.y = fmaf(s1, inv, m.y);
    o1.x = fmaf(s2, inv, m.x); o1.y = fmaf(s3, inv, m.y);
    *(float2*)(out + (size_t)grow * ND + col) = o0;
    *(float2*)(out + (size_t)(grow + 8) * ND + col) = o1;
}

extern "C" void kernel_launch(void* const* d_in, const int* in_sizes, int n_in,
                              void* d_out, int out_size)
{
    const float* x = (const float*)d_in[0];
    const float* W = (const float*)d_in[1];
    const float* b = (const float*)d_in[2];
    float* out = (float*)d_out;

    transform_kernel<<<TBLOCKS, TTHREADS>>>(x, W, b);

    cudaLaunchConfig_t cfg = {};
    cfg.gridDim  = dim3(MBLOCKS, 1, 1);
    cfg.blockDim = dim3(MTHREADS, 1, 1);
    cfg.dynamicSmemBytes = 0;
    cudaLaunchAttribute attrs[1];
    attrs[0].id = cudaLaunchAttributeProgrammaticStreamSerialization;
    attrs[0].val.programmaticStreamSerializationAllowed = 1;
    cfg.attrs = attrs;
    cfg.numAttrs = 1;
    cudaLaunchKernelEx(&cfg, nanembed_hmma_kernel, out);
}

// round 16
// speedup vs baseline: 1.7672x; 1.3821x over previous
#include <cuda_runtime.h>
#include <cstdint>

// out[n,d] = mean_f( x[n,f]*W[f,d] + b[f,d] ) = (x@W)[n,d]/256 + mean_f b[f,d]
// N=8192, K=256, D=64. Single kernel. bf16 3-term split, mma.sync m16n8k16.
// R4 skeleton with: all load streams (x DRAM, W L2, b L2) issued before any
// conversion; 6 independent accumulators; 1-deep LDSM pipeline.

typedef uint32_t u32;

#define NROWS  8192
#define NF     256
#define ND     64
#define TILE_M 32
#define THREADS 256
#define NBLOCKS (NROWS / TILE_M)   // 256

// padded bf16 pitches (bytes): conflict-free ldmatrix
#define XPITCHB (264 * 2)   // 528
#define WPITCHB (72 * 2)    // 144

#define XH_OFF 0
#define XL_OFF (XH_OFF + TILE_M * XPITCHB)   // 16896
#define WH_OFF (XL_OFF + TILE_M * XPITCHB)   // 33792
#define WL_OFF (WH_OFF + NF * WPITCHB)       // 70656
#define MB_OFF (WL_OFF + NF * WPITCHB)       // 107520
#define SC_OFF (MB_OFF + 256)                // 107776
#define SMEM_BYTES (SC_OFF + 4096)           // 111872

__device__ __forceinline__ u32 smem_u32(const void* p) {
    u32 a;
    asm("{ .reg .u64 t; cvta.to.shared.u64 t, %1; cvt.u32.u64 %0, t; }" : "=r"(a) : "l"(p));
    return a;
}
__device__ __forceinline__ void cvt_split(float a, float b, u32& hi, u32& lo) {
    asm("cvt.rn.bf16x2.f32 %0, %1, %2;" : "=r"(hi) : "f"(b), "f"(a));
    float ha = __uint_as_float(hi << 16);
    float hb = __uint_as_float(hi & 0xFFFF0000u);
    float ra = a - ha;
    float rb = b - hb;
    asm("cvt.rn.bf16x2.f32 %0, %1, %2;" : "=r"(lo) : "f"(rb), "f"(ra));
}
__device__ __forceinline__ void ldsm4(u32* r, u32 addr) {
    asm volatile("ldmatrix.sync.aligned.m8n8.x4.shared.b16 {%0,%1,%2,%3}, [%4];"
        : "=r"(r[0]), "=r"(r[1]), "=r"(r[2]), "=r"(r[3]) : "r"(addr));
}
__device__ __forceinline__ void ldsm4t(u32* r, u32 addr) {
    asm volatile("ldmatrix.sync.aligned.m8n8.x4.trans.shared.b16 {%0,%1,%2,%3}, [%4];"
        : "=r"(r[0]), "=r"(r[1]), "=r"(r[2]), "=r"(r[3]) : "r"(addr));
}
__device__ __forceinline__ void mma16816(float* c, const u32* a, u32 b0, u32 b1) {
    asm volatile(
        "mma.sync.aligned.m16n8k16.row.col.f32.bf16.bf16.f32 "
        "{%0,%1,%2,%3}, {%4,%5,%6,%7}, {%8,%9}, {%0,%1,%2,%3};"
        : "+f"(c[0]), "+f"(c[1]), "+f"(c[2]), "+f"(c[3])
        : "r"(a[0]), "r"(a[1]), "r"(a[2]), "r"(a[3]), "r"(b0), "r"(b1));
}

__global__ void __launch_bounds__(THREADS, 2)
nanembed_hmma_kernel(const float* __restrict__ x,
                     const float* __restrict__ W,
                     const float* __restrict__ b,
                     float* __restrict__ out)
{
    extern __shared__ char smem[];
    const u32 sb = smem_u32(smem);
    const int tid = threadIdx.x;

    // ---- 1) issue x tile loads (DRAM, 8 float4/thread) ----
    const float4* x4 = (const float4*)(x + (size_t)blockIdx.x * TILE_M * NF);
    float4 xv[8];
    #pragma unroll
    for (int i = 0; i < 8; ++i)
        xv[i] = x4[tid + THREADS * i];

    // ---- 2) issue W batch 1 loads (L2, 8 float4/thread) ----
    const float4* W4 = (const float4*)W;
    float4 wv[8];
    #pragma unroll
    for (int i = 0; i < 8; ++i)
        wv[i] = W4[tid + THREADS * i];

    // ---- 3) convert x -> XH/XL (x DRAM stall absorbed here; W1 in flight) ----
    #pragma unroll
    for (int i = 0; i < 8; ++i) {
        int idx = tid + THREADS * i;
        int row = idx >> 6;
        int c4  = idx & 63;
        u32 h0, l0, h1, l1;
        cvt_split(xv[i].x, xv[i].y, h0, l0);
        cvt_split(xv[i].z, xv[i].w, h1, l1);
        u32 off = (u32)(row * XPITCHB + c4 * 8);
        asm volatile("st.shared.v2.b32 [%0], {%1, %2};"
                     :: "r"(sb + XH_OFF + off), "r"(h0), "r"(h1) : "memory");
        asm volatile("st.shared.v2.b32 [%0], {%1, %2};"
                     :: "r"(sb + XL_OFF + off), "r"(l0), "r"(l1) : "memory");
    }

    // ---- 4) convert W batch 1, issue W batch 2 ----
    float4 wv2[8];
    #pragma unroll
    for (int i = 0; i < 8; ++i)
        wv2[i] = W4[2048 + tid + THREADS * i];
    #pragma unroll
    for (int i = 0; i < 8; ++i) {
        int idx = tid + THREADS * i;          // 0..2047
        int row = idx >> 4;                   // 16 float4 per W row
        int c4  = idx & 15;
        u32 h0, l0, h1, l1;
        cvt_split(wv[i].x, wv[i].y, h0, l0);
        cvt_split(wv[i].z, wv[i].w, h1, l1);
        u32 off = (u32)(row * WPITCHB + c4 * 8);
        asm volatile("st.shared.v2.b32 [%0], {%1, %2};"
                     :: "r"(sb + WH_OFF + off), "r"(h0), "r"(h1) : "memory");
        asm volatile("st.shared.v2.b32 [%0], {%1, %2};"
                     :: "r"(sb + WL_OFF + off), "r"(l0), "r"(l1) : "memory");
    }

    // ---- 5) issue b partial loads, convert W batch 2 ----
    const int qd = tid & 15;
    const int fr = tid >> 4;
    const float4* b4 = (const float4*)b;   // [256][16] float4
    float4 bv[8];
    #pragma unroll
    for (int k = 0; k < 8; ++k)
        bv[k] = b4[(fr * 16 + k) * 16 + qd];

    #pragma unroll
    for (int i = 0; i < 8; ++i) {
        int idx = 2048 + tid + THREADS * i;   // 2048..4095
        int row = idx >> 4;
        int c4  = idx & 15;
        u32 h0, l0, h1, l1;
        cvt_split(wv2[i].x, wv2[i].y, h0, l0);
        cvt_split(wv2[i].z, wv2[i].w, h1, l1);
        u32 off = (u32)(row * WPITCHB + c4 * 8);
        asm volatile("st.shared.v2.b32 [%0], {%1, %2};"
                     :: "r"(sb + WH_OFF + off), "r"(h0), "r"(h1) : "memory");
        asm volatile("st.shared.v2.b32 [%0], {%1, %2};"
                     :: "r"(sb + WL_OFF + off), "r"(l0), "r"(l1) : "memory");
    }

    // ---- 6) b partial sums -> scratch ----
    {
        float4 s = make_float4(0.f, 0.f, 0.f, 0.f);
        #pragma unroll
        for (int k = 0; k < 8; ++k) {
            s.x += bv[k].x; s.y += bv[k].y; s.z += bv[k].z; s.w += bv[k].w;
            bv[k] = b4[(fr * 16 + 8 + k) * 16 + qd];
        }
        #pragma unroll
        for (int k = 0; k < 8; ++k) {
            s.x += bv[k].x; s.y += bv[k].y; s.z += bv[k].z; s.w += bv[k].w;
        }
        ((float4*)(smem + SC_OFF))[tid] = s;
    }
    __syncthreads();
    if (tid < 16) {
        float4* sc = (float4*)(smem + SC_OFF);
        float4 m = make_float4(0.f, 0.f, 0.f, 0.f);
        #pragma unroll
        for (int g = 0; g < 16; ++g) {
            float4 v = sc[tid + 16 * g];
            m.x += v.x; m.y += v.y; m.z += v.z; m.w += v.w;
        }
        const float inv = 1.f / 256.f;
        m.x *= inv; m.y *= inv; m.z *= inv; m.w *= inv;
        ((float4*)(smem + MB_OFF))[tid] = m;
    }
    __syncthreads();

    // ---- mainloop: warp = 16 rows x 16 cols, 6 independent acc chains ----
    const int wid  = tid >> 5;
    const int lane = tid & 31;
    const int r0   = (wid & 1) * 16;
    const int n0   = (wid >> 1) * 16;
    const int g    = lane >> 2;
    const int t4   = lane & 3;

    const u32 aRow = (u32)(r0 + (lane & 15));
    const u32 aCol = (u32)((lane >> 4) * 16);
    u32 aAddrH = sb + XH_OFF + aRow * XPITCHB + aCol;
    u32 aAddrL = aAddrH + (u32)(XL_OFF - XH_OFF);
    const u32 bRow = (u32)(lane & 15);
    const u32 bCol = (u32)(n0 * 2 + (lane >> 4) * 16);
    u32 bAddrH = sb + WH_OFF + bRow * WPITCHB + bCol;
    u32 bAddrL = bAddrH + (u32)(WL_OFF - WH_OFF);

    float a0hh[4]={0,0,0,0}, a0hl[4]={0,0,0,0}, a0lh[4]={0,0,0,0};
    float a1hh[4]={0,0,0,0}, a1hl[4]={0,0,0,0}, a1lh[4]={0,0,0,0};

    u32 ah[2][4], al[2][4], bh[2][4], bl[2][4];
    ldsm4 (ah[0], aAddrH);
    ldsm4 (al[0], aAddrL);
    ldsm4t(bh[0], bAddrH);
    ldsm4t(bl[0], bAddrL);

    #pragma unroll
    for (int ki = 0; ki < 16; ++ki) {
        const int cur = ki & 1;
        const int nxt = cur ^ 1;
        if (ki < 15) {
            ldsm4 (ah[nxt], aAddrH + (u32)(ki + 1) * 32);
            ldsm4 (al[nxt], aAddrL + (u32)(ki + 1) * 32);
            ldsm4t(bh[nxt], bAddrH + (u32)(ki + 1) * (16 * WPITCHB));
            ldsm4t(bl[nxt], bAddrL + (u32)(ki + 1) * (16 * WPITCHB));
        }
        mma16816(a0hh, ah[cur], bh[cur][0], bh[cur][1]);
        mma16816(a1hh, ah[cur], bh[cur][2], bh[cur][3]);
        mma16816(a0hl, ah[cur], bl[cur][0], bl[cur][1]);
        mma16816(a1hl, ah[cur], bl[cur][2], bl[cur][3]);
        mma16816(a0lh, al[cur], bh[cur][0], bh[cur][1]);
        mma16816(a1lh, al[cur], bh[cur][2], bh[cur][3]);
    }

    // ---- epilogue: combine terms, scale, add bias-mean ----
    const float* mb = (const float*)(smem + MB_OFF);
    const float inv = 1.f / 256.f;
    const int grow = blockIdx.x * TILE_M + r0 + g;
    {
        int col = n0 + 2 * t4;
        float2 m = *(const float2*)(mb + col);
        float s0 = a0hh[0] + a0hl[0] + a0lh[0];
        float s1 = a0hh[1] + a0hl[1] + a0lh[1];
        float s2 = a0hh[2] + a0hl[2] + a0lh[2];
        float s3 = a0hh[3] + a0hl[3] + a0lh[3];
        float2 o0, o1;
        o0.x = fmaf(s0, inv, m.x); o0.y = fmaf(s1, inv, m.y);
        o1.x = fmaf(s2, inv, m.x); o1.y = fmaf(s3, inv, m.y);
        *(float2*)(out + (size_t)grow * ND + col) = o0;
        *(float2*)(out + (size_t)(grow + 8) * ND + col) = o1;
    }
    {
        int col = n0 + 8 + 2 * t4;
        float2 m = *(const float2*)(mb + col);
        float s0 = a1hh[0] + a1hl[0] + a1lh[0];
        float s1 = a1hh[1] + a1hl[1] + a1lh[1];
        float s2 = a1hh[2] + a1hl[2] + a1lh[2];
        float s3 = a1hh[3] + a1hl[3] + a1lh[3];
        float2 o0, o1;
        o0.x = fmaf(s0, inv, m.x); o0.y = fmaf(s1, inv, m.y);
        o1.x = fmaf(s2, inv, m.x); o1.y = fmaf(s3, inv, m.y);
        *(float2*)(out + (size_t)grow * ND + col) = o0;
        *(float2*)(out + (size_t)(grow + 8) * ND + col) = o1;
    }
}

extern "C" void kernel_launch(void* const* d_in, const int* in_sizes, int n_in,
                              void* d_out, int out_size)
{
    const float* x = (const float*)d_in[0];
    const float* W = (const float*)d_in[1];
    const float* b = (const float*)d_in[2];
    float* out = (float*)d_out;

    cudaFuncSetAttribute(nanembed_hmma_kernel,
                         cudaFuncAttributeMaxDynamicSharedMemorySize, SMEM_BYTES);
    nanembed_hmma_kernel<<<NBLOCKS, THREADS, SMEM_BYTES>>>(x, W, b, out);
}